// round 2
// baseline (speedup 1.0000x reference)
#include <cuda_runtime.h>
#include <cuda_bf16.h>
#include <cstdint>

#define N_NODES 50000
#define IN_F 128
#define OUT_F 128
#define N_EDGES 800000
#define ALPHA 0.2f
#define EPS 1e-16f

// ---------------- device scratch (static, no allocation) ----------------
__device__ __align__(16) float g_Wh[(size_t)N_NODES * OUT_F];   // 25.6 MB
__device__ float g_s1[N_NODES];
__device__ float g_s2[N_NODES];
__device__ float g_rowsum[N_NODES];
__device__ float g_expsum[N_NODES];
__device__ float g_e[N_EDGES];
__device__ float g_ee[N_EDGES];
__device__ __align__(8) int2 g_rc[N_EDGES];

// ---------------- K1: Wh = h @ W, fused s1/s2 epilogue ----------------
// 256 threads/block, block computes 64 rows x 128 cols.
__global__ __launch_bounds__(256) void gat_gemm_kernel(
    const float* __restrict__ h, const float* __restrict__ W,
    const float* __restrict__ a)
{
    __shared__ float hs[64][36];     // 64 rows x 32 k (padded)
    __shared__ float Ws[32 * 128];   // k-tile x 128 cols

    const int tid = threadIdx.x;
    const int tx = tid & 31;
    const int ty = tid >> 5;
    const int row0 = blockIdx.x * 64;

    float acc[8][4];
#pragma unroll
    for (int r = 0; r < 8; r++)
#pragma unroll
        for (int c = 0; c < 4; c++) acc[r][c] = 0.0f;

    for (int kt = 0; kt < IN_F; kt += 32) {
        const float4* Wg = reinterpret_cast<const float4*>(W + kt * OUT_F);
        float4* Wsv = reinterpret_cast<float4*>(Ws);
#pragma unroll
        for (int i = 0; i < 4; i++) Wsv[tid + 256 * i] = Wg[tid + 256 * i];

#pragma unroll
        for (int i = 0; i < 2; i++) {
            int idx = tid + 256 * i;      // 0..511
            int r = idx >> 3;             // 0..63
            int cc = (idx & 7) * 4;       // 0..28
            int gr = row0 + r;
            float4 v = make_float4(0.f, 0.f, 0.f, 0.f);
            if (gr < N_NODES)
                v = *reinterpret_cast<const float4*>(h + (size_t)gr * IN_F + kt + cc);
            *reinterpret_cast<float4*>(&hs[r][cc]) = v;
        }
        __syncthreads();

#pragma unroll
        for (int k = 0; k < 32; k++) {
            float4 w = *reinterpret_cast<const float4*>(Ws + k * 128 + tx * 4);
#pragma unroll
            for (int r = 0; r < 8; r++) {
                float hv = hs[ty * 8 + r][k];
                acc[r][0] += hv * w.x;
                acc[r][1] += hv * w.y;
                acc[r][2] += hv * w.z;
                acc[r][3] += hv * w.w;
            }
        }
        __syncthreads();
    }

    float4 a1 = *reinterpret_cast<const float4*>(a + tx * 4);
    float4 a2 = *reinterpret_cast<const float4*>(a + OUT_F + tx * 4);

#pragma unroll
    for (int r = 0; r < 8; r++) {
        int gr = row0 + ty * 8 + r;
        float p1 = acc[r][0] * a1.x + acc[r][1] * a1.y + acc[r][2] * a1.z + acc[r][3] * a1.w;
        float p2 = acc[r][0] * a2.x + acc[r][1] * a2.y + acc[r][2] * a2.z + acc[r][3] * a2.w;
#pragma unroll
        for (int off = 16; off > 0; off >>= 1) {
            p1 += __shfl_xor_sync(0xFFFFFFFFu, p1, off);
            p2 += __shfl_xor_sync(0xFFFFFFFFu, p2, off);
        }
        if (gr < N_NODES) {
            *reinterpret_cast<float4*>(g_Wh + (size_t)gr * OUT_F + tx * 4) =
                make_float4(acc[r][0], acc[r][1], acc[r][2], acc[r][3]);
            if (tx == 0) { g_s1[gr] = p1; g_s2[gr] = p2; }
        }
    }
}

// ---------------- zero kernels ----------------
__global__ void zero_sums_kernel()
{
    int i = blockIdx.x * blockDim.x + threadIdx.x;
    if (i < N_NODES) { g_rowsum[i] = 0.0f; g_expsum[i] = 0.0f; }
}

__global__ void zero_out_kernel(float4* __restrict__ out, int n4)
{
    int i = blockIdx.x * blockDim.x + threadIdx.x;
    int stride = gridDim.x * blockDim.x;
    for (; i < n4; i += stride) out[i] = make_float4(0.f, 0.f, 0.f, 0.f);
}

// ---------------- edge pass A: e = lrelu(s1[row]+s2[col]), rowsum ----------------
// edge_index is int32 on device (JAX x64 disabled demotes int64 -> int32).
__global__ __launch_bounds__(256) void edge_a_kernel(const int* __restrict__ ei)
{
    int i = blockIdx.x * blockDim.x + threadIdx.x;
    if (i >= N_EDGES) return;
    int r = ei[i];
    int c = ei[N_EDGES + i];
    g_rc[i] = make_int2(r, c);
    float e = g_s1[r] + g_s2[c];
    e = (e > 0.0f) ? e : ALPHA * e;
    g_e[i] = e;
    atomicAdd(&g_rowsum[r], e);
}

// ---------------- edge pass B: ee = exp(e - rowsum[row]), expsum ----------------
__global__ __launch_bounds__(256) void edge_b_kernel()
{
    int i = blockIdx.x * blockDim.x + threadIdx.x;
    if (i >= N_EDGES) return;
    int2 rc = g_rc[i];
    float ee = __expf(g_e[i] - g_rowsum[rc.x]);
    g_ee[i] = ee;
    atomicAdd(&g_expsum[rc.x], ee);
}

// ---------------- edge pass C: out[row] += att * Wh[col], warp per edge ----------------
__global__ __launch_bounds__(256) void edge_c_kernel(float* __restrict__ out)
{
    int e = (blockIdx.x * blockDim.x + threadIdx.x) >> 5;
    if (e >= N_EDGES) return;
    int lane = threadIdx.x & 31;
    int2 rc = g_rc[e];
    float att = g_ee[e] / (g_expsum[rc.x] + EPS);
    float4 v = *reinterpret_cast<const float4*>(g_Wh + (size_t)rc.y * OUT_F + lane * 4);
    float ox = att * v.x, oy = att * v.y, oz = att * v.z, ow = att * v.w;
    float* dst = out + (size_t)rc.x * OUT_F + lane * 4;
    asm volatile("red.global.add.v4.f32 [%0], {%1, %2, %3, %4};"
                 :: "l"(dst), "f"(ox), "f"(oy), "f"(oz), "f"(ow)
                 : "memory");
}

// ---------------- launch ----------------
extern "C" void kernel_launch(void* const* d_in, const int* in_sizes, int n_in,
                              void* d_out, int out_size)
{
    const float* h  = (const float*)d_in[0];
    const int*   ei = (const int*)d_in[1];
    const float* W  = (const float*)d_in[2];
    const float* a  = (const float*)d_in[3];
    float* out = (float*)d_out;

    gat_gemm_kernel<<<(N_NODES + 63) / 64, 256>>>(h, W, a);

    zero_sums_kernel<<<(N_NODES + 255) / 256, 256>>>();
    int n4 = (N_NODES * OUT_F) / 4;
    zero_out_kernel<<<1024, 256>>>((float4*)out, n4);

    edge_a_kernel<<<(N_EDGES + 255) / 256, 256>>>(ei);
    edge_b_kernel<<<(N_EDGES + 255) / 256, 256>>>();
    edge_c_kernel<<<(N_EDGES * 32 + 255) / 256, 256>>>(out);
}